// round 8
// baseline (speedup 1.0000x reference)
#include <cuda_runtime.h>
#include <cuda_bf16.h>
#include <cstdint>

#define N_ATOMS 10000
#define N_PAIRS 250000
#define NPROP   128

typedef unsigned long long u64;

// ---------------- f32x2 packed helpers (sm_100+) ----------------
__device__ __forceinline__ u64 pk2(float lo, float hi) {
    u64 r; asm("mov.b64 %0,{%1,%2};" : "=l"(r) : "f"(lo), "f"(hi)); return r;
}
__device__ __forceinline__ void upk2(u64 v, float& lo, float& hi) {
    asm("mov.b64 {%0,%1},%2;" : "=f"(lo), "=f"(hi) : "l"(v));
}
__device__ __forceinline__ u64 fma2(u64 a, u64 b, u64 c) {
    u64 r; asm("fma.rn.f32x2 %0,%1,%2,%3;" : "=l"(r) : "l"(a), "l"(b), "l"(c)); return r;
}
__device__ __forceinline__ u64 add2(u64 a, u64 b) {
    u64 r; asm("add.rn.f32x2 %0,%1,%2;" : "=l"(r) : "l"(a), "l"(b)); return r;
}
__device__ __forceinline__ u64 mul2(u64 a, u64 b) {
    u64 r; asm("mul.rn.f32x2 %0,%1,%2;" : "=l"(r) : "l"(a), "l"(b)); return r;
}

// ---------------- device scratch (static, allocation-free) ----------------
// Zero-initialized at module load; k_scan re-zeroes counts/cursor each call.
__device__ int   g_counts[N_ATOMS];
__device__ int   g_cursor[N_ATOMS];
__device__ int   g_offsets[N_ATOMS + 1];
__device__ int   g_pairlist[N_PAIRS];
__device__ float g_pxacc[(size_t)N_ATOMS * 3 * NPROP];

// ---------------- K1: histogram of ind_i ----------------
__global__ void k_hist(const int* __restrict__ ind2) {
    int p = blockIdx.x * blockDim.x + threadIdx.x;
    if (p < N_PAIRS) atomicAdd(&g_counts[ind2[2 * p]], 1);
}

// ---------------- K2: exclusive scan + self-cleaning (1 block) ------------
__global__ void k_scan() {
    __shared__ int part[1024];
    const int PER = 10;
    int t = threadIdx.x;
    int local[PER];
    int sum = 0;
#pragma unroll
    for (int r = 0; r < PER; r++) {
        int idx = t * PER + r;
        int v = 0;
        if (idx < N_ATOMS) {
            v = g_counts[idx];
            g_counts[idx] = 0;
            g_cursor[idx] = 0;
        }
        local[r] = sum;
        sum += v;
    }
    part[t] = sum;
    __syncthreads();
    for (int off = 1; off < 1024; off <<= 1) {
        int v = (t >= off) ? part[t - off] : 0;
        __syncthreads();
        part[t] += v;
        __syncthreads();
    }
    int base = (t > 0) ? part[t - 1] : 0;
#pragma unroll
    for (int r = 0; r < PER; r++) {
        int idx = t * PER + r;
        if (idx < N_ATOMS) g_offsets[idx] = base + local[r];
    }
    if (t == 1023) g_offsets[N_ATOMS] = part[1023];
}

// ---------------- K3: scatter pair ids into CSR ----------------
__global__ void k_scatter(const int* __restrict__ ind2) {
    int p = blockIdx.x * blockDim.x + threadIdx.x;
    if (p < N_PAIRS) {
        int i = ind2[2 * p];
        int pos = atomicAdd(&g_cursor[i], 1);
        g_pairlist[g_offsets[i] + pos] = p;
    }
}

// ---------------- K4: hot kernel — sort + ix + per-atom segment sum -------
// 256-thread blocks (8 warps, one atom each), regs capped for 48 warps/SM
// resident -> more loads in flight -> higher DRAM utilization. Segment
// sorted in shared (deterministic), consumed from shared. Simple body
// (2-pair pipeline removed: measured neutral, cost registers).
__global__ void __launch_bounds__(256, 6) k_accum(
        const int*   __restrict__ ind2,
        const float* __restrict__ px,
        const float* __restrict__ i1,
        const float* __restrict__ diff,
        float*       __restrict__ ix) {
    __shared__ int buf[8][96];
    int wd   = threadIdx.x >> 5;
    int lane = threadIdx.x & 31;
    int a = blockIdx.x * 8 + wd;              // grid = N_ATOMS/8 exactly
    int s = g_offsets[a], e = g_offsets[a + 1];
    int n = e - s;

    // stage + sort segment in shared (deterministic order)
    const int* plist;
    if (n <= 96) {
        for (int i = lane; i < n; i += 32) buf[wd][i] = g_pairlist[s + i];
        __syncwarp();
        for (int r = 0; r < n; r++) {
            int start = r & 1;
            for (int i = start + 2 * lane; i + 1 < n; i += 64) {
                int x = buf[wd][i], y = buf[wd][i + 1];
                if (x > y) { buf[wd][i] = y; buf[wd][i + 1] = x; }
            }
            __syncwarp();
        }
        plist = buf[wd];
    } else {
        if (lane == 0) {                       // overflow fallback (P~0)
            for (int i = s + 1; i < e; i++) {
                int v = g_pairlist[i];
                int j = i - 1;
                while (j >= s && g_pairlist[j] > v) { g_pairlist[j + 1] = g_pairlist[j]; j--; }
                g_pairlist[j + 1] = v;
            }
        }
        __syncwarp();
        plist = &g_pairlist[s];
    }

    float4 a0 = make_float4(0.f, 0.f, 0.f, 0.f);
    float4 a1 = a0, a2 = a0;

    for (int k = 0; k < n; k++) {
        int p = plist[k];
        int j = __ldg(&ind2[2 * p + 1]);
        float4 sv = __ldcs((const float4*)(i1 + (size_t)p * NPROP) + lane);
        float d0 = __ldg(&diff[3 * p + 0]);
        float d1 = __ldg(&diff[3 * p + 1]);
        float d2 = __ldg(&diff[3 * p + 2]);
        const float4* pxj = (const float4*)(px + (size_t)j * 3 * NPROP);
        float4 p0 = __ldg(pxj + lane);
        float4 p1 = __ldg(pxj + 32 + lane);
        float4 p2 = __ldg(pxj + 64 + lane);

        float4 v0, v1, v2;
        v0.x = fmaf(p0.x, sv.x, d0 * sv.x); v0.y = fmaf(p0.y, sv.y, d0 * sv.y);
        v0.z = fmaf(p0.z, sv.z, d0 * sv.z); v0.w = fmaf(p0.w, sv.w, d0 * sv.w);
        v1.x = fmaf(p1.x, sv.x, d1 * sv.x); v1.y = fmaf(p1.y, sv.y, d1 * sv.y);
        v1.z = fmaf(p1.z, sv.z, d1 * sv.z); v1.w = fmaf(p1.w, sv.w, d1 * sv.w);
        v2.x = fmaf(p2.x, sv.x, d2 * sv.x); v2.y = fmaf(p2.y, sv.y, d2 * sv.y);
        v2.z = fmaf(p2.z, sv.z, d2 * sv.z); v2.w = fmaf(p2.w, sv.w, d2 * sv.w);

        float4* op = (float4*)(ix + (size_t)p * 3 * NPROP);
        __stcs(op + lane,      v0);
        __stcs(op + 32 + lane, v1);
        __stcs(op + 64 + lane, v2);

        a0.x += v0.x; a0.y += v0.y; a0.z += v0.z; a0.w += v0.w;
        a1.x += v1.x; a1.y += v1.y; a1.z += v1.z; a1.w += v1.w;
        a2.x += v2.x; a2.y += v2.y; a2.z += v2.z; a2.w += v2.w;
    }

    float4* ap = (float4*)(g_pxacc + (size_t)a * 3 * NPROP);
    ap[lane]      = a0;
    ap[32 + lane] = a1;
    ap[64 + lane] = a2;
}

// ---------------- K5: px_new = acc @ w_pp, dotted = sum_x px_new^2 --------
// f32x2 packed FMA with PRE-DUPLICATED accumulator staging: the (v,v) packs
// happen once per atom (staging), the 128-c inner loop is pure
// 4x LDS.64 (3 broadcast) + 3x fma.rn.f32x2 -> fma-pipe time halved.
__global__ void __launch_bounds__(128) k_gemm(
        const float* __restrict__ w,
        float*       __restrict__ pxnew,
        float*       __restrict__ dotted) {
    __shared__ float sw[128 * 64];            // 32KB: w[:, qh*64 .. qh*64+63]
    __shared__ u64   sax[4][NPROP];           // 4KB: (x0,x0) per c, per warp
    __shared__ u64   say[4][NPROP];           // 4KB
    __shared__ u64   saz[4][NPROP];           // 4KB  -> 44KB total static

    int tid = threadIdx.x, wd = tid >> 5, lane = tid & 31;
    int qh = blockIdx.y;

    for (int i = tid; i < 2048; i += 128) {
        int c = i >> 4, f4 = i & 15;
        ((float4*)sw)[i] = __ldg((const float4*)(w + (size_t)c * NPROP + qh * 64) + f4);
    }
    __syncthreads();

    const u64* sw2 = (const u64*)sw;          // lane's float2 of q per c

    int abase = blockIdx.x * 32 + wd * 8;
    for (int t = 0; t < 8; t++) {
        int a = abase + t;
        if (a >= N_ATOMS) break;
        const float* ap = g_pxacc + (size_t)a * 3 * NPROP;
#pragma unroll
        for (int r = 0; r < 4; r++) {
            int c = lane + 32 * r;
            float x = ap[c], y = ap[NPROP + c], z = ap[2 * NPROP + c];
            sax[wd][c] = pk2(x, x);
            say[wd][c] = pk2(y, y);
            saz[wd][c] = pk2(z, z);
        }
        __syncwarp();

        u64 o0 = 0, o1 = 0, o2 = 0;
#pragma unroll 8
        for (int c = 0; c < NPROP; c++) {
            u64 wv = sw2[c * 32 + lane];
            o0 = fma2(sax[wd][c], wv, o0);
            o1 = fma2(say[wd][c], wv, o1);
            o2 = fma2(saz[wd][c], wv, o2);
        }

        float* pn = pxnew + (size_t)a * 3 * NPROP + qh * 64;
        ((u64*)pn)[lane]               = o0;
        ((u64*)(pn + NPROP))[lane]     = o1;
        ((u64*)(pn + 2 * NPROP))[lane] = o2;

        u64 dv = add2(add2(mul2(o0, o0), mul2(o1, o1)), mul2(o2, o2));
        ((u64*)(dotted + (size_t)a * NPROP + qh * 64))[lane] = dv;
        __syncwarp();
    }
}

// ---------------- launch (5 kernels; k_accum = overall launch #6 -> ncu) --
extern "C" void kernel_launch(void* const* d_in, const int* in_sizes, int n_in,
                              void* d_out, int out_size) {
    const int*   ind2 = (const int*)  d_in[0];
    const float* px   = (const float*)d_in[1];
    const float* i1   = (const float*)d_in[2];
    const float* diff = (const float*)d_in[3];
    const float* w    = (const float*)d_in[4];

    float* out   = (float*)d_out;
    float* pxnew = out;                                  // 10000*3*128
    float* ixo   = out + 3840000LL;                      // 250000*3*128
    float* dot   = out + 99840000LL;                     // 10000*128

    k_hist   <<<(N_PAIRS + 255) / 256, 256>>>(ind2);
    k_scan   <<<1, 1024>>>();
    k_scatter<<<(N_PAIRS + 255) / 256, 256>>>(ind2);
    k_accum  <<<N_ATOMS / 8, 256>>>(ind2, px, i1, diff, ixo);

    dim3 gg((N_ATOMS + 31) / 32, 2);
    k_gemm   <<<gg, 128>>>(w, pxnew, dot);
}

// round 9
// speedup vs baseline: 1.2894x; 1.2894x over previous
#include <cuda_runtime.h>
#include <cuda_bf16.h>
#include <cstdint>

#define N_ATOMS 10000
#define N_PAIRS 250000
#define NPROP   128

typedef unsigned long long u64;

// ---------------- f32x2 packed helpers (sm_100+) ----------------
__device__ __forceinline__ u64 pk2(float lo, float hi) {
    u64 r; asm("mov.b64 %0,{%1,%2};" : "=l"(r) : "f"(lo), "f"(hi)); return r;
}
__device__ __forceinline__ u64 fma2(u64 a, u64 b, u64 c) {
    u64 r; asm("fma.rn.f32x2 %0,%1,%2,%3;" : "=l"(r) : "l"(a), "l"(b), "l"(c)); return r;
}
__device__ __forceinline__ u64 add2(u64 a, u64 b) {
    u64 r; asm("add.rn.f32x2 %0,%1,%2;" : "=l"(r) : "l"(a), "l"(b)); return r;
}
__device__ __forceinline__ u64 mul2(u64 a, u64 b) {
    u64 r; asm("mul.rn.f32x2 %0,%1,%2;" : "=l"(r) : "l"(a), "l"(b)); return r;
}

// ---------------- device scratch (static, allocation-free) ----------------
// Zero-initialized at module load; k_scan re-zeroes counts/cursor each call.
__device__ int   g_counts[N_ATOMS];
__device__ int   g_cursor[N_ATOMS];
__device__ int   g_offsets[N_ATOMS + 1];
__device__ int   g_pairlist[N_PAIRS];
__device__ float g_pxacc[(size_t)N_ATOMS * 3 * NPROP];

// ---------------- K1: histogram of ind_i ----------------
__global__ void k_hist(const int* __restrict__ ind2) {
    int p = blockIdx.x * blockDim.x + threadIdx.x;
    if (p < N_PAIRS) atomicAdd(&g_counts[ind2[2 * p]], 1);
}

// ---------------- K2: exclusive scan + self-cleaning (1 block) ------------
__global__ void k_scan() {
    __shared__ int part[1024];
    const int PER = 10;
    int t = threadIdx.x;
    int local[PER];
    int sum = 0;
#pragma unroll
    for (int r = 0; r < PER; r++) {
        int idx = t * PER + r;
        int v = 0;
        if (idx < N_ATOMS) {
            v = g_counts[idx];
            g_counts[idx] = 0;
            g_cursor[idx] = 0;
        }
        local[r] = sum;
        sum += v;
    }
    part[t] = sum;
    __syncthreads();
    for (int off = 1; off < 1024; off <<= 1) {
        int v = (t >= off) ? part[t - off] : 0;
        __syncthreads();
        part[t] += v;
        __syncthreads();
    }
    int base = (t > 0) ? part[t - 1] : 0;
#pragma unroll
    for (int r = 0; r < PER; r++) {
        int idx = t * PER + r;
        if (idx < N_ATOMS) g_offsets[idx] = base + local[r];
    }
    if (t == 1023) g_offsets[N_ATOMS] = part[1023];
}

// ---------------- K3: scatter pair ids into CSR ----------------
__global__ void k_scatter(const int* __restrict__ ind2) {
    int p = blockIdx.x * blockDim.x + threadIdx.x;
    if (p < N_PAIRS) {
        int i = ind2[2 * p];
        int pos = atomicAdd(&g_cursor[i], 1);
        g_pairlist[g_offsets[i] + pos] = p;
    }
}

// ---------------- K4: hot kernel — sort + ix + per-atom segment sum -------
// EXACT R7 form (measured 100.8us, DRAM 62%): 128-thr blocks, natural regs,
// warp-per-atom, segment sorted+consumed in shared, __stcs streaming stores.
__global__ void __launch_bounds__(128) k_accum(
        const int*   __restrict__ ind2,
        const float* __restrict__ px,
        const float* __restrict__ i1,
        const float* __restrict__ diff,
        float*       __restrict__ ix) {
    __shared__ int buf[4][96];
    int wd   = threadIdx.x >> 5;
    int lane = threadIdx.x & 31;
    int a = blockIdx.x * 4 + wd;              // grid = N_ATOMS/4 exactly
    int s = g_offsets[a], e = g_offsets[a + 1];
    int n = e - s;

    const int* plist;
    if (n <= 96) {
        for (int i = lane; i < n; i += 32) buf[wd][i] = g_pairlist[s + i];
        __syncwarp();
        for (int r = 0; r < n; r++) {
            int start = r & 1;
            for (int i = start + 2 * lane; i + 1 < n; i += 64) {
                int x = buf[wd][i], y = buf[wd][i + 1];
                if (x > y) { buf[wd][i] = y; buf[wd][i + 1] = x; }
            }
            __syncwarp();
        }
        plist = buf[wd];
    } else {
        if (lane == 0) {                       // overflow fallback (P~0)
            for (int i = s + 1; i < e; i++) {
                int v = g_pairlist[i];
                int j = i - 1;
                while (j >= s && g_pairlist[j] > v) { g_pairlist[j + 1] = g_pairlist[j]; j--; }
                g_pairlist[j + 1] = v;
            }
        }
        __syncwarp();
        plist = &g_pairlist[s];
    }

    float4 a0 = make_float4(0.f, 0.f, 0.f, 0.f);
    float4 a1 = a0, a2 = a0;

    int pA = 0, jA = 0, pB = 0, jB = 0;
    if (n > 0) { pA = plist[0]; jA = __ldg(&ind2[2 * pA + 1]); }
    if (n > 1) { pB = plist[1]; jB = __ldg(&ind2[2 * pB + 1]); }

    int k = 0;
    for (; k + 1 < n; k += 2) {
        int pa = pA, ja = jA, pb = pB, jb = jB;
        if (k + 2 < n) { pA = plist[k + 2]; jA = __ldg(&ind2[2 * pA + 1]); }
        if (k + 3 < n) { pB = plist[k + 3]; jB = __ldg(&ind2[2 * pB + 1]); }
        {
            int p = pa, j = ja;
            float4 sv = __ldcs((const float4*)(i1 + (size_t)p * NPROP) + lane);
            float d0 = __ldg(&diff[3 * p + 0]);
            float d1 = __ldg(&diff[3 * p + 1]);
            float d2 = __ldg(&diff[3 * p + 2]);
            const float4* pxj = (const float4*)(px + (size_t)j * 3 * NPROP);
            float4 p0 = __ldg(pxj + lane);
            float4 p1 = __ldg(pxj + 32 + lane);
            float4 p2 = __ldg(pxj + 64 + lane);
            float4 v0, v1, v2;
            v0.x = fmaf(p0.x, sv.x, d0 * sv.x); v0.y = fmaf(p0.y, sv.y, d0 * sv.y);
            v0.z = fmaf(p0.z, sv.z, d0 * sv.z); v0.w = fmaf(p0.w, sv.w, d0 * sv.w);
            v1.x = fmaf(p1.x, sv.x, d1 * sv.x); v1.y = fmaf(p1.y, sv.y, d1 * sv.y);
            v1.z = fmaf(p1.z, sv.z, d1 * sv.z); v1.w = fmaf(p1.w, sv.w, d1 * sv.w);
            v2.x = fmaf(p2.x, sv.x, d2 * sv.x); v2.y = fmaf(p2.y, sv.y, d2 * sv.y);
            v2.z = fmaf(p2.z, sv.z, d2 * sv.z); v2.w = fmaf(p2.w, sv.w, d2 * sv.w);
            float4* op = (float4*)(ix + (size_t)p * 3 * NPROP);
            __stcs(op + lane,      v0);
            __stcs(op + 32 + lane, v1);
            __stcs(op + 64 + lane, v2);
            a0.x += v0.x; a0.y += v0.y; a0.z += v0.z; a0.w += v0.w;
            a1.x += v1.x; a1.y += v1.y; a1.z += v1.z; a1.w += v1.w;
            a2.x += v2.x; a2.y += v2.y; a2.z += v2.z; a2.w += v2.w;
        }
        {
            int p = pb, j = jb;
            float4 sv = __ldcs((const float4*)(i1 + (size_t)p * NPROP) + lane);
            float d0 = __ldg(&diff[3 * p + 0]);
            float d1 = __ldg(&diff[3 * p + 1]);
            float d2 = __ldg(&diff[3 * p + 2]);
            const float4* pxj = (const float4*)(px + (size_t)j * 3 * NPROP);
            float4 p0 = __ldg(pxj + lane);
            float4 p1 = __ldg(pxj + 32 + lane);
            float4 p2 = __ldg(pxj + 64 + lane);
            float4 v0, v1, v2;
            v0.x = fmaf(p0.x, sv.x, d0 * sv.x); v0.y = fmaf(p0.y, sv.y, d0 * sv.y);
            v0.z = fmaf(p0.z, sv.z, d0 * sv.z); v0.w = fmaf(p0.w, sv.w, d0 * sv.w);
            v1.x = fmaf(p1.x, sv.x, d1 * sv.x); v1.y = fmaf(p1.y, sv.y, d1 * sv.y);
            v1.z = fmaf(p1.z, sv.z, d1 * sv.z); v1.w = fmaf(p1.w, sv.w, d1 * sv.w);
            v2.x = fmaf(p2.x, sv.x, d2 * sv.x); v2.y = fmaf(p2.y, sv.y, d2 * sv.y);
            v2.z = fmaf(p2.z, sv.z, d2 * sv.z); v2.w = fmaf(p2.w, sv.w, d2 * sv.w);
            float4* op = (float4*)(ix + (size_t)p * 3 * NPROP);
            __stcs(op + lane,      v0);
            __stcs(op + 32 + lane, v1);
            __stcs(op + 64 + lane, v2);
            a0.x += v0.x; a0.y += v0.y; a0.z += v0.z; a0.w += v0.w;
            a1.x += v1.x; a1.y += v1.y; a1.z += v1.z; a1.w += v1.w;
            a2.x += v2.x; a2.y += v2.y; a2.z += v2.z; a2.w += v2.w;
        }
    }
    if (k < n) {
        int p = pA, j = jA;
        float4 sv = __ldcs((const float4*)(i1 + (size_t)p * NPROP) + lane);
        float d0 = __ldg(&diff[3 * p + 0]);
        float d1 = __ldg(&diff[3 * p + 1]);
        float d2 = __ldg(&diff[3 * p + 2]);
        const float4* pxj = (const float4*)(px + (size_t)j * 3 * NPROP);
        float4 p0 = __ldg(pxj + lane);
        float4 p1 = __ldg(pxj + 32 + lane);
        float4 p2 = __ldg(pxj + 64 + lane);
        float4 v0, v1, v2;
        v0.x = fmaf(p0.x, sv.x, d0 * sv.x); v0.y = fmaf(p0.y, sv.y, d0 * sv.y);
        v0.z = fmaf(p0.z, sv.z, d0 * sv.z); v0.w = fmaf(p0.w, sv.w, d0 * sv.w);
        v1.x = fmaf(p1.x, sv.x, d1 * sv.x); v1.y = fmaf(p1.y, sv.y, d1 * sv.y);
        v1.z = fmaf(p1.z, sv.z, d1 * sv.z); v1.w = fmaf(p1.w, sv.w, d1 * sv.w);
        v2.x = fmaf(p2.x, sv.x, d2 * sv.x); v2.y = fmaf(p2.y, sv.y, d2 * sv.y);
        v2.z = fmaf(p2.z, sv.z, d2 * sv.z); v2.w = fmaf(p2.w, sv.w, d2 * sv.w);
        float4* op = (float4*)(ix + (size_t)p * 3 * NPROP);
        __stcs(op + lane,      v0);
        __stcs(op + 32 + lane, v1);
        __stcs(op + 64 + lane, v2);
        a0.x += v0.x; a0.y += v0.y; a0.z += v0.z; a0.w += v0.w;
        a1.x += v1.x; a1.y += v1.y; a1.z += v1.z; a1.w += v1.w;
        a2.x += v2.x; a2.y += v2.y; a2.z += v2.z; a2.w += v2.w;
    }

    float4* ap = (float4*)(g_pxacc + (size_t)a * 3 * NPROP);
    ap[lane]      = a0;
    ap[32 + lane] = a1;
    ap[64 + lane] = a2;
}

// ---------------- K5: px_new = acc @ w_pp, dotted = sum_x px_new^2 --------
// v3: 2 atoms per inner loop + f32x2 FMAs. Duplication done in REGISTERS
// (pk2 on alu pipe, overlaps fma pipe) — not in shared (R8's mistake).
// Per c per 2 atoms: LDS = wv u64 (2cyc) + 2 float4 bcasts (2cyc) = 4 cyc;
// 6 fma2 = 3 cyc fma; 6 pk2 = 3 cyc alu. LDS-bound ~2 cyc/atom/c (half of R7).
__global__ void __launch_bounds__(128) k_gemm(
        const float* __restrict__ w,
        float*       __restrict__ pxnew,
        float*       __restrict__ dotted) {
    __shared__ float  sw[128 * 64];           // 32KB: w[:, qh*64 .. qh*64+63]
    __shared__ float4 sacc[4][2][NPROP];      // 16KB: per warp, 2 staged atoms

    int tid = threadIdx.x, wd = tid >> 5, lane = tid & 31;
    int qh = blockIdx.y;

    for (int i = tid; i < 2048; i += 128) {
        int c = i >> 4, f4 = i & 15;
        ((float4*)sw)[i] = __ldg((const float4*)(w + (size_t)c * NPROP + qh * 64) + f4);
    }
    __syncthreads();

    const u64* sw2 = (const u64*)sw;          // lane's 2 q per c

    int abase = blockIdx.x * 32 + wd * 8;     // 8 atoms per warp, in pairs
    for (int t = 0; t < 4; t++) {
        int a0i = abase + 2 * t;              // N_ATOMS % 8 == 0: pair valid together
        if (a0i >= N_ATOMS) break;
        int a1i = a0i + 1;

        const float* apA = g_pxacc + (size_t)a0i * 3 * NPROP;
        const float* apB = g_pxacc + (size_t)a1i * 3 * NPROP;
#pragma unroll
        for (int r = 0; r < 4; r++) {
            int c = lane + 32 * r;
            sacc[wd][0][c] = make_float4(apA[c], apA[NPROP + c], apA[2 * NPROP + c], 0.f);
            sacc[wd][1][c] = make_float4(apB[c], apB[NPROP + c], apB[2 * NPROP + c], 0.f);
        }
        __syncwarp();

        u64 ox0 = 0, oy0 = 0, oz0 = 0;        // atom0: 3 rows x lane's 2 q
        u64 ox1 = 0, oy1 = 0, oz1 = 0;        // atom1
#pragma unroll 4
        for (int c = 0; c < NPROP; c++) {
            u64 wv = sw2[c * 32 + lane];
            float4 vA = sacc[wd][0][c];
            float4 vB = sacc[wd][1][c];
            ox0 = fma2(pk2(vA.x, vA.x), wv, ox0);
            oy0 = fma2(pk2(vA.y, vA.y), wv, oy0);
            oz0 = fma2(pk2(vA.z, vA.z), wv, oz0);
            ox1 = fma2(pk2(vB.x, vB.x), wv, ox1);
            oy1 = fma2(pk2(vB.y, vB.y), wv, oy1);
            oz1 = fma2(pk2(vB.z, vB.z), wv, oz1);
        }

        float* pn0 = pxnew + (size_t)a0i * 3 * NPROP + qh * 64;
        ((u64*)pn0)[lane]               = ox0;
        ((u64*)(pn0 + NPROP))[lane]     = oy0;
        ((u64*)(pn0 + 2 * NPROP))[lane] = oz0;
        float* pn1 = pxnew + (size_t)a1i * 3 * NPROP + qh * 64;
        ((u64*)pn1)[lane]               = ox1;
        ((u64*)(pn1 + NPROP))[lane]     = oy1;
        ((u64*)(pn1 + 2 * NPROP))[lane] = oz1;

        u64 dv0 = add2(add2(mul2(ox0, ox0), mul2(oy0, oy0)), mul2(oz0, oz0));
        u64 dv1 = add2(add2(mul2(ox1, ox1), mul2(oy1, oy1)), mul2(oz1, oz1));
        ((u64*)(dotted + (size_t)a0i * NPROP + qh * 64))[lane] = dv0;
        ((u64*)(dotted + (size_t)a1i * NPROP + qh * 64))[lane] = dv1;
        __syncwarp();
    }
}

// ---------------- launch (5 kernels; k_accum = overall launch #6 -> ncu) --
extern "C" void kernel_launch(void* const* d_in, const int* in_sizes, int n_in,
                              void* d_out, int out_size) {
    const int*   ind2 = (const int*)  d_in[0];
    const float* px   = (const float*)d_in[1];
    const float* i1   = (const float*)d_in[2];
    const float* diff = (const float*)d_in[3];
    const float* w    = (const float*)d_in[4];

    float* out   = (float*)d_out;
    float* pxnew = out;                                  // 10000*3*128
    float* ixo   = out + 3840000LL;                      // 250000*3*128
    float* dot   = out + 99840000LL;                     // 10000*128

    k_hist   <<<(N_PAIRS + 255) / 256, 256>>>(ind2);
    k_scan   <<<1, 1024>>>();
    k_scatter<<<(N_PAIRS + 255) / 256, 256>>>(ind2);
    k_accum  <<<N_ATOMS / 4, 128>>>(ind2, px, i1, diff, ixo);

    dim3 gg((N_ATOMS + 31) / 32, 2);
    k_gemm   <<<gg, 128>>>(w, pxnew, dot);
}

// round 10
// speedup vs baseline: 1.4019x; 1.0872x over previous
#include <cuda_runtime.h>
#include <cuda_bf16.h>
#include <cstdint>

#define N_ATOMS 10000
#define N_PAIRS 250000
#define NPROP   128

typedef unsigned long long u64;

// ---------------- f32x2 packed helpers (sm_100+) ----------------
__device__ __forceinline__ u64 pk2(float lo, float hi) {
    u64 r; asm("mov.b64 %0,{%1,%2};" : "=l"(r) : "f"(lo), "f"(hi)); return r;
}
__device__ __forceinline__ u64 fma2(u64 a, u64 b, u64 c) {
    u64 r; asm("fma.rn.f32x2 %0,%1,%2,%3;" : "=l"(r) : "l"(a), "l"(b), "l"(c)); return r;
}
__device__ __forceinline__ u64 add2(u64 a, u64 b) {
    u64 r; asm("add.rn.f32x2 %0,%1,%2;" : "=l"(r) : "l"(a), "l"(b)); return r;
}
__device__ __forceinline__ u64 mul2(u64 a, u64 b) {
    u64 r; asm("mul.rn.f32x2 %0,%1,%2;" : "=l"(r) : "l"(a), "l"(b)); return r;
}

// ---------------- device scratch (static, allocation-free) ----------------
// Zero-initialized at load; each kernel leaves state clean for next replay.
__device__ int   g_counts[N_ATOMS];   // hist writes; alloc reads+zeroes
__device__ int   g_nums[N_ATOMS];     // segment length (overwritten each run)
__device__ int   g_offsets[N_ATOMS];  // segment base  (overwritten each run)
__device__ int   g_cursor[N_ATOMS];   // scatter cursor, seeded to base
__device__ int   g_total;             // allocation counter (reset in hist)
__device__ int   g_pairlist[N_PAIRS];
__device__ float g_pxacc[(size_t)N_ATOMS * 3 * NPROP];

// ---------------- K1: histogram of ind_i (int4 = 2 pairs / thread) --------
__global__ void k_hist(const int* __restrict__ ind2) {
    int t = blockIdx.x * blockDim.x + threadIdx.x;
    if (t == 0) g_total = 0;                    // reset allocator for this run
    int base = t * 2;                           // pairs [base, base+1]
    if (base + 1 < N_PAIRS) {
        int4 v = __ldg((const int4*)(ind2 + 2 * base));
        atomicAdd(&g_counts[v.x], 1);
        atomicAdd(&g_counts[v.z], 1);
    } else if (base < N_PAIRS) {
        atomicAdd(&g_counts[ind2[2 * base]], 1);
    }
}

// ---------------- K2: parallel segment allocation (order-free) ------------
// Disjoint CSR segments via block scan + one atomicAdd per block for the
// base. Offsets are NOT globally ordered — doesn't matter, k_accum sorts
// each segment's contents before summing, so output stays deterministic.
__global__ void __launch_bounds__(1024) k_alloc() {
    __shared__ int wtot[32];
    __shared__ int blockbase;
    int t = threadIdx.x, lane = t & 31, wid = t >> 5;
    int idx = blockIdx.x * 1024 + t;

    int c = (idx < N_ATOMS) ? g_counts[idx] : 0;

    // warp inclusive scan
    int incl = c;
#pragma unroll
    for (int off = 1; off < 32; off <<= 1) {
        int v = __shfl_up_sync(0xffffffff, incl, off);
        if (lane >= off) incl += v;
    }
    if (lane == 31) wtot[wid] = incl;
    __syncthreads();

    // scan the 32 warp totals in warp 0
    if (wid == 0) {
        int v = wtot[lane];
        int wincl = v;
#pragma unroll
        for (int off = 1; off < 32; off <<= 1) {
            int u = __shfl_up_sync(0xffffffff, wincl, off);
            if (lane >= off) wincl += u;
        }
        wtot[lane] = wincl - v;                 // exclusive warp base
        if (lane == 31) blockbase = atomicAdd(&g_total, wincl);
    }
    __syncthreads();

    if (idx < N_ATOMS) {
        int offs = blockbase + wtot[wid] + (incl - c);
        g_offsets[idx] = offs;
        g_cursor[idx]  = offs;                  // scatter adds from base
        g_nums[idx]    = c;
        g_counts[idx]  = 0;                     // clean for next replay
    }
}

// ---------------- K3: scatter pair ids into CSR ----------------
__global__ void k_scatter(const int* __restrict__ ind2) {
    int p = blockIdx.x * blockDim.x + threadIdx.x;
    if (p < N_PAIRS) {
        int i = ind2[2 * p];
        int pos = atomicAdd(&g_cursor[i], 1);
        g_pairlist[pos] = p;
    }
}

// ---------------- K4: hot kernel — sort + ix + per-atom segment sum -------
// Warp-per-atom, segment sorted+consumed in shared, simple loop (2-pair
// pipeline removed: measured neutral, costs regs -> occupancy).
__global__ void __launch_bounds__(128) k_accum(
        const int*   __restrict__ ind2,
        const float* __restrict__ px,
        const float* __restrict__ i1,
        const float* __restrict__ diff,
        float*       __restrict__ ix) {
    __shared__ int buf[4][96];
    int wd   = threadIdx.x >> 5;
    int lane = threadIdx.x & 31;
    int a = blockIdx.x * 4 + wd;              // grid = N_ATOMS/4 exactly
    int s = g_offsets[a];
    int n = g_nums[a];

    const int* plist;
    if (n <= 96) {
        for (int i = lane; i < n; i += 32) buf[wd][i] = g_pairlist[s + i];
        __syncwarp();
        for (int r = 0; r < n; r++) {
            int start = r & 1;
            for (int i = start + 2 * lane; i + 1 < n; i += 64) {
                int x = buf[wd][i], y = buf[wd][i + 1];
                if (x > y) { buf[wd][i] = y; buf[wd][i + 1] = x; }
            }
            __syncwarp();
        }
        plist = buf[wd];
    } else {
        if (lane == 0) {                       // overflow fallback (P~0)
            int e = s + n;
            for (int i = s + 1; i < e; i++) {
                int v = g_pairlist[i];
                int j = i - 1;
                while (j >= s && g_pairlist[j] > v) { g_pairlist[j + 1] = g_pairlist[j]; j--; }
                g_pairlist[j + 1] = v;
            }
        }
        __syncwarp();
        plist = &g_pairlist[s];
    }

    float4 a0 = make_float4(0.f, 0.f, 0.f, 0.f);
    float4 a1 = a0, a2 = a0;

    for (int k = 0; k < n; k++) {
        int p = plist[k];
        int j = __ldg(&ind2[2 * p + 1]);
        float4 sv = __ldcs((const float4*)(i1 + (size_t)p * NPROP) + lane);
        float d0 = __ldg(&diff[3 * p + 0]);
        float d1 = __ldg(&diff[3 * p + 1]);
        float d2 = __ldg(&diff[3 * p + 2]);
        const float4* pxj = (const float4*)(px + (size_t)j * 3 * NPROP);
        float4 p0 = __ldg(pxj + lane);
        float4 p1 = __ldg(pxj + 32 + lane);
        float4 p2 = __ldg(pxj + 64 + lane);

        float4 v0, v1, v2;
        v0.x = fmaf(p0.x, sv.x, d0 * sv.x); v0.y = fmaf(p0.y, sv.y, d0 * sv.y);
        v0.z = fmaf(p0.z, sv.z, d0 * sv.z); v0.w = fmaf(p0.w, sv.w, d0 * sv.w);
        v1.x = fmaf(p1.x, sv.x, d1 * sv.x); v1.y = fmaf(p1.y, sv.y, d1 * sv.y);
        v1.z = fmaf(p1.z, sv.z, d1 * sv.z); v1.w = fmaf(p1.w, sv.w, d1 * sv.w);
        v2.x = fmaf(p2.x, sv.x, d2 * sv.x); v2.y = fmaf(p2.y, sv.y, d2 * sv.y);
        v2.z = fmaf(p2.z, sv.z, d2 * sv.z); v2.w = fmaf(p2.w, sv.w, d2 * sv.w);

        float4* op = (float4*)(ix + (size_t)p * 3 * NPROP);
        __stcs(op + lane,      v0);
        __stcs(op + 32 + lane, v1);
        __stcs(op + 64 + lane, v2);

        a0.x += v0.x; a0.y += v0.y; a0.z += v0.z; a0.w += v0.w;
        a1.x += v1.x; a1.y += v1.y; a1.z += v1.z; a1.w += v1.w;
        a2.x += v2.x; a2.y += v2.y; a2.z += v2.z; a2.w += v2.w;
    }

    float4* ap = (float4*)(g_pxacc + (size_t)a * 3 * NPROP);
    ap[lane]      = a0;
    ap[32 + lane] = a1;
    ap[64 + lane] = a2;
}

// ---------------- K5: px_new = acc @ w_pp, dotted = sum_x px_new^2 --------
// R9 version (validated): 2 atoms/iter, f32x2 FMAs, register duplication.
__global__ void __launch_bounds__(128) k_gemm(
        const float* __restrict__ w,
        float*       __restrict__ pxnew,
        float*       __restrict__ dotted) {
    __shared__ float  sw[128 * 64];           // 32KB: w[:, qh*64 .. qh*64+63]
    __shared__ float4 sacc[4][2][NPROP];      // 16KB: per warp, 2 staged atoms

    int tid = threadIdx.x, wd = tid >> 5, lane = tid & 31;
    int qh = blockIdx.y;

    for (int i = tid; i < 2048; i += 128) {
        int c = i >> 4, f4 = i & 15;
        ((float4*)sw)[i] = __ldg((const float4*)(w + (size_t)c * NPROP + qh * 64) + f4);
    }
    __syncthreads();

    const u64* sw2 = (const u64*)sw;

    int abase = blockIdx.x * 32 + wd * 8;
    for (int t = 0; t < 4; t++) {
        int a0i = abase + 2 * t;
        if (a0i >= N_ATOMS) break;
        int a1i = a0i + 1;

        const float* apA = g_pxacc + (size_t)a0i * 3 * NPROP;
        const float* apB = g_pxacc + (size_t)a1i * 3 * NPROP;
#pragma unroll
        for (int r = 0; r < 4; r++) {
            int c = lane + 32 * r;
            sacc[wd][0][c] = make_float4(apA[c], apA[NPROP + c], apA[2 * NPROP + c], 0.f);
            sacc[wd][1][c] = make_float4(apB[c], apB[NPROP + c], apB[2 * NPROP + c], 0.f);
        }
        __syncwarp();

        u64 ox0 = 0, oy0 = 0, oz0 = 0;
        u64 ox1 = 0, oy1 = 0, oz1 = 0;
#pragma unroll 4
        for (int c = 0; c < NPROP; c++) {
            u64 wv = sw2[c * 32 + lane];
            float4 vA = sacc[wd][0][c];
            float4 vB = sacc[wd][1][c];
            ox0 = fma2(pk2(vA.x, vA.x), wv, ox0);
            oy0 = fma2(pk2(vA.y, vA.y), wv, oy0);
            oz0 = fma2(pk2(vA.z, vA.z), wv, oz0);
            ox1 = fma2(pk2(vB.x, vB.x), wv, ox1);
            oy1 = fma2(pk2(vB.y, vB.y), wv, oy1);
            oz1 = fma2(pk2(vB.z, vB.z), wv, oz1);
        }

        float* pn0 = pxnew + (size_t)a0i * 3 * NPROP + qh * 64;
        ((u64*)pn0)[lane]               = ox0;
        ((u64*)(pn0 + NPROP))[lane]     = oy0;
        ((u64*)(pn0 + 2 * NPROP))[lane] = oz0;
        float* pn1 = pxnew + (size_t)a1i * 3 * NPROP + qh * 64;
        ((u64*)pn1)[lane]               = ox1;
        ((u64*)(pn1 + NPROP))[lane]     = oy1;
        ((u64*)(pn1 + 2 * NPROP))[lane] = oz1;

        u64 dv0 = add2(add2(mul2(ox0, ox0), mul2(oy0, oy0)), mul2(oz0, oz0));
        u64 dv1 = add2(add2(mul2(ox1, ox1), mul2(oy1, oy1)), mul2(oz1, oz1));
        ((u64*)(dotted + (size_t)a0i * NPROP + qh * 64))[lane] = dv0;
        ((u64*)(dotted + (size_t)a1i * NPROP + qh * 64))[lane] = dv1;
        __syncwarp();
    }
}

// ---------------- launch (5 kernels; k_accum = overall launch #6 -> ncu) --
extern "C" void kernel_launch(void* const* d_in, const int* in_sizes, int n_in,
                              void* d_out, int out_size) {
    const int*   ind2 = (const int*)  d_in[0];
    const float* px   = (const float*)d_in[1];
    const float* i1   = (const float*)d_in[2];
    const float* diff = (const float*)d_in[3];
    const float* w    = (const float*)d_in[4];

    float* out   = (float*)d_out;
    float* pxnew = out;                                  // 10000*3*128
    float* ixo   = out + 3840000LL;                      // 250000*3*128
    float* dot   = out + 99840000LL;                     // 10000*128

    k_hist   <<<(N_PAIRS / 2 + 255) / 256, 256>>>(ind2);
    k_alloc  <<<(N_ATOMS + 1023) / 1024, 1024>>>();
    k_scatter<<<(N_PAIRS + 255) / 256, 256>>>(ind2);
    k_accum  <<<N_ATOMS / 4, 128>>>(ind2, px, i1, diff, ixo);

    dim3 gg((N_ATOMS + 31) / 32, 2);
    k_gemm   <<<gg, 128>>>(w, pxnew, dot);
}